// round 10
// baseline (speedup 1.0000x reference)
#include <cuda_runtime.h>
#include <math.h>

#define Nn   100000
#define Ee   1600000
#define NH   (Nn * 64)
#define CHUNK 676   // ceil(100000/148)

typedef unsigned long long ull;
__device__ __forceinline__ ull bcast2(float x) {
    ull r; asm("mov.b64 %0, {%1, %1};" : "=l"(r) : "f"(x)); return r;
}
__device__ __forceinline__ void ffma2(ull& d, ull a, ull b) {
    asm("fma.rn.f32x2 %0, %1, %2, %0;" : "+l"(d) : "l"(a), "l"(b));
}
__device__ __forceinline__ float2 unpk(ull v) {
    float2 f; asm("mov.b64 {%0, %1}, %2;" : "=f"(f.x), "=f"(f.y) : "l"(v)); return f;
}

// ---- persistent device scratch ----
__device__ float g_dinv[Nn];
__device__ int   g_cnt[Nn];
__device__ int   g_off[Nn];
__device__ int   g_cur[Nn];
__device__ int   g_bsum[256];
__device__ int2  g_csr[Ee];
__device__ float g_hb[3][NH];
__device__ float g_seq[(size_t)Nn * 256];
__device__ float g_Mt[4096];
__device__ float g_Wvo[4096];
__device__ float g_p2[64];
__device__ float g_bvo[64];

// ---- grid-wide barriers (separate state per kernel) ----
__device__ unsigned g_barcnt1 = 0;
__device__ volatile unsigned g_barsense1 = 0;
__device__ unsigned g_barcnt2 = 0;
__device__ volatile unsigned g_barsense2 = 0;

__device__ __forceinline__ void gridbar(unsigned& sense, unsigned* cnt,
                                        volatile unsigned* gsense) {
    __threadfence();
    __syncthreads();
    if (threadIdx.x == 0) {
        sense ^= 1u;
        unsigned old = atomicAdd(cnt, 1u);
        if (old == gridDim.x - 1) {
            atomicExch(cnt, 0u);
            __threadfence();
            *gsense = sense;
        } else {
            while (*gsense != sense) { }
        }
    }
    __syncthreads();
}

// ================= single-kernel CSR build + dinv + folded matrices =================
__global__ void __launch_bounds__(256) k_build(
    const int* __restrict__ src, const int* __restrict__ dst,
    const float* __restrict__ inW, const float* __restrict__ inb,
    const float* __restrict__ WoutG, const float* __restrict__ boutG) {
    __shared__ int part[256];
    int tid = threadIdx.x, cta = blockIdx.x;
    int gs = gridDim.x * 256;
    unsigned sense = g_barsense1;

    // phase 0: folded attention matrices (independent of graph)
    for (int e = cta * 256 + tid; e < 4096; e += gs) {
        int bcol = e >> 6, a = e & 63;
        float m = 0.f, wv = 0.f;
        for (int j = 0; j < 64; j++) {
            m  = fmaf(__ldg(inW + j * 64 + a),   __ldg(inW + (64 + j) * 64 + bcol), m);
            wv = fmaf(__ldg(WoutG + a * 64 + j), __ldg(inW + (128 + j) * 64 + bcol), wv);
        }
        g_Mt[e] = m;
        g_Wvo[e] = wv;
    }
    if (cta == 147) {
        if (tid < 64) {
            float p = 0.f;
            for (int j = 0; j < 64; j++) p = fmaf(__ldg(inb + j), __ldg(inW + (64 + j) * 64 + tid), p);
            g_p2[tid] = p;
        } else if (tid < 128) {
            int a = tid - 64;
            float bv = __ldg(boutG + a);
            for (int j = 0; j < 64; j++) bv = fmaf(__ldg(WoutG + a * 64 + j), __ldg(inb + 128 + j), bv);
            g_bvo[a] = bv;
        }
    }
    // phase 1: zero counts
    for (int i = cta * 256 + tid; i < Nn; i += gs) g_cnt[i] = 0;
    gridbar(sense, &g_barcnt1, &g_barsense1);
    // phase 2: count degrees
    for (int e = cta * 256 + tid; e < Ee; e += gs) atomicAdd(&g_cnt[dst[e]], 1);
    gridbar(sense, &g_barcnt1, &g_barsense1);
    // phase 3: per-CTA partial sums over contiguous chunk
    int base = cta * CHUNK;
    int lim = min(base + CHUNK, Nn);
    int i0 = base + tid * 3;
    int c0 = (i0     < lim) ? g_cnt[i0]     : 0;
    int c1 = (i0 + 1 < lim) ? g_cnt[i0 + 1] : 0;
    int c2 = (i0 + 2 < lim) ? g_cnt[i0 + 2] : 0;
    int tsum = c0 + c1 + c2;
    part[tid] = tsum;
    __syncthreads();
    for (int off = 1; off < 256; off <<= 1) {
        int v = (tid >= off) ? part[tid - off] : 0;
        __syncthreads();
        if (tid >= off) part[tid] += v;
        __syncthreads();
    }
    if (tid == 255) g_bsum[cta] = part[255];
    gridbar(sense, &g_barcnt1, &g_barsense1);
    // phase 4: CTA0 scans CTA partials
    if (cta == 0 && tid == 0) {
        int acc = 0;
        for (int b = 0; b < (int)gridDim.x; b++) { int t = g_bsum[b]; g_bsum[b] = acc; acc += t; }
    }
    gridbar(sense, &g_barcnt1, &g_barsense1);
    // phase 5: write offsets / cursors / dinv
    {
        int ctaoff = g_bsum[cta];
        int texcl = ctaoff + part[tid] - tsum;
        if (i0 < lim) {
            g_off[i0] = texcl; g_cur[i0] = texcl;
            g_dinv[i0] = rsqrtf((float)c0 + 1.0f);
        }
        if (i0 + 1 < lim) {
            int ex = texcl + c0;
            g_off[i0 + 1] = ex; g_cur[i0 + 1] = ex;
            g_dinv[i0 + 1] = rsqrtf((float)c1 + 1.0f);
        }
        if (i0 + 2 < lim) {
            int ex = texcl + c0 + c1;
            g_off[i0 + 2] = ex; g_cur[i0 + 2] = ex;
            g_dinv[i0 + 2] = rsqrtf((float)c2 + 1.0f);
        }
    }
    gridbar(sense, &g_barcnt1, &g_barsense1);
    // phase 6: fill CSR
    for (int e = cta * 256 + tid; e < Ee; e += gs) {
        int s = src[e], d = dst[e];
        int pos = atomicAdd(&g_cur[d], 1);
        g_csr[pos] = make_int2(s, __float_as_int(g_dinv[s]));
    }
}

// ================= h0 = relu(x @ W_in^T + b_in) =================
__global__ void k_in_linear(const float* __restrict__ x, const float* __restrict__ W,
                            const float* __restrict__ b) {
    extern __shared__ float sm[];
    float* Ws = sm;                 // [64][260]
    float* bb = Ws + 64 * 260;
    float* xb = bb + 64;
    int tid = threadIdx.x;
    for (int i = tid; i < 64 * 64; i += 256) {
        int j = i >> 6, q = i & 63;
        ((float4*)(Ws + j * 260))[q] = ((const float4*)(W + j * 256))[q];
    }
    if (tid < 64) bb[tid] = b[tid];
    __syncthreads();
    int warp = tid >> 5, l = tid & 31;
    float* xw = xb + warp * 1024;
    const float* w0p = Ws + l * 260;
    const float* w1p = Ws + (l + 32) * 260;
    for (int grp = blockIdx.x * 8 + warp; grp < 25000; grp += gridDim.x * 8) {
        int row0 = grp * 4;
        const float4* xg = (const float4*)(x + (size_t)row0 * 256);
        #pragma unroll
        for (int r = 0; r < 4; r++) {
            ((float4*)xw)[r * 64 + l]      = xg[r * 64 + l];
            ((float4*)xw)[r * 64 + l + 32] = xg[r * 64 + l + 32];
        }
        __syncwarp();
        float acc0[4], acc1[4];
        #pragma unroll
        for (int r = 0; r < 4; r++) { acc0[r] = bb[l]; acc1[r] = bb[l + 32]; }
        #pragma unroll 4
        for (int k4 = 0; k4 < 64; k4++) {
            float4 wa = ((const float4*)w0p)[k4];
            float4 wb = ((const float4*)w1p)[k4];
            #pragma unroll
            for (int r = 0; r < 4; r++) {
                float4 xv = ((const float4*)(xw + r * 256))[k4];
                acc0[r] = fmaf(xv.x, wa.x, acc0[r]);
                acc0[r] = fmaf(xv.y, wa.y, acc0[r]);
                acc0[r] = fmaf(xv.z, wa.z, acc0[r]);
                acc0[r] = fmaf(xv.w, wa.w, acc0[r]);
                acc1[r] = fmaf(xv.x, wb.x, acc1[r]);
                acc1[r] = fmaf(xv.y, wb.y, acc1[r]);
                acc1[r] = fmaf(xv.z, wb.z, acc1[r]);
                acc1[r] = fmaf(xv.w, wb.w, acc1[r]);
            }
        }
        #pragma unroll
        for (int r = 0; r < 4; r++) {
            float a0 = fmaxf(acc0[r], 0.f), a1 = fmaxf(acc1[r], 0.f);
            size_t row = row0 + r;
            g_hb[0][row * 64 + l]      = a0;
            g_hb[0][row * 64 + l + 32] = a1;
            g_seq[row * 256 + l]       = a0;
            g_seq[row * 256 + l + 32]  = a1;
        }
        __syncwarp();
    }
}

// ================= fused 3-hop gather-propagate + token linears (persistent) =================
// grid 592 = 4 CTAs/SM, all resident; grid barrier between hops.
__global__ void __launch_bounds__(256, 4) k_prop_all(const float* __restrict__ sgW,
                                                     const float* __restrict__ sgb) {
    __shared__ float Wt[4096];
    __shared__ float bb[64];
    __shared__ float pbuf[8][2][64];
    __shared__ int2  ebuf[8][32];
    int tid = threadIdx.x;
    int warp = tid >> 5, l = tid & 31;
    int half = l >> 4, q = l & 15;
    int2* eb = ebuf[warp];
    unsigned sense = g_barsense2;

    const int ib[3] = {0, 1, 2};
    const int ob[3] = {1, 2, 1};

    for (int hop = 0; hop < 3; hop++) {
        // load this hop's weights (previous hop's users are past gridbar's syncthreads)
        const float* W = sgW + hop * 4096;
        for (int i = tid; i < 4096; i += 256) {
            int k = i >> 6, j = i & 63;
            Wt[i] = W[j * 64 + k];
        }
        if (tid < 64) bb[tid] = sgb[hop * 64 + tid];
        __syncthreads();

        const float* hin = g_hb[ib[hop]];
        float* hout = g_hb[ob[hop]];
        int slot = hop + 1;

        for (int pair = blockIdx.x * 8 + warp; pair < 50000; pair += gridDim.x * 8) {
            int n = pair * 2 + half;
            int beg = g_off[n], cnt = g_cnt[n];
            float dn = g_dinv[n];
            float4 acc = ((const float4*)(hin + (size_t)n * 64))[q];
            acc.x *= dn; acc.y *= dn; acc.z *= dn; acc.w *= dn;
            int cntO = __shfl_xor_sync(0xffffffffu, cnt, 16);
            int cmax = cnt > cntO ? cnt : cntO;
            for (int chunk = 0; chunk < cmax; chunk += 16) {
                if (chunk + q < cnt) eb[l] = __ldg(&g_csr[beg + chunk + q]);
                __syncwarp();
                int m = min(16, cnt - chunk);
                int base = half * 16;
                int i = 0;
                for (; i + 4 <= m; i += 4) {
                    float4 v[4]; float w[4];
                    #pragma unroll
                    for (int u = 0; u < 4; u++) {
                        int2 e = eb[base + i + u];
                        v[u] = __ldg((const float4*)(hin + (size_t)e.x * 64) + q);
                        w[u] = __int_as_float(e.y);
                    }
                    #pragma unroll
                    for (int u = 0; u < 4; u++) {
                        acc.x = fmaf(w[u], v[u].x, acc.x);
                        acc.y = fmaf(w[u], v[u].y, acc.y);
                        acc.z = fmaf(w[u], v[u].z, acc.z);
                        acc.w = fmaf(w[u], v[u].w, acc.w);
                    }
                }
                for (; i < m; i++) {
                    int2 e = eb[base + i];
                    float4 v0 = __ldg((const float4*)(hin + (size_t)e.x * 64) + q);
                    float w0 = __int_as_float(e.y);
                    acc.x = fmaf(w0, v0.x, acc.x);
                    acc.y = fmaf(w0, v0.y, acc.y);
                    acc.z = fmaf(w0, v0.z, acc.z);
                    acc.w = fmaf(w0, v0.w, acc.w);
                }
                __syncwarp();
            }
            acc.x *= dn; acc.y *= dn; acc.z *= dn; acc.w *= dn;
            ((float4*)(hout + (size_t)n * 64))[q] = acc;
            ((float4*)pbuf[warp][half])[q] = acc;
            __syncwarp();
            const float* pw = pbuf[warp][half];
            float4 tac = *(const float4*)(bb + q * 4);
            #pragma unroll 4
            for (int k4 = 0; k4 < 16; k4++) {
                float4 xv = ((const float4*)pw)[k4];
                #pragma unroll
                for (int kk = 0; kk < 4; kk++) {
                    float4 w = *(const float4*)(Wt + (k4 * 4 + kk) * 64 + q * 4);
                    float xk = kk == 0 ? xv.x : kk == 1 ? xv.y : kk == 2 ? xv.z : xv.w;
                    tac.x = fmaf(xk, w.x, tac.x);
                    tac.y = fmaf(xk, w.y, tac.y);
                    tac.z = fmaf(xk, w.z, tac.z);
                    tac.w = fmaf(xk, w.w, tac.w);
                }
            }
            tac.x = fmaxf(tac.x, 0.f); tac.y = fmaxf(tac.y, 0.f);
            tac.z = fmaxf(tac.z, 0.f); tac.w = fmaxf(tac.w, 0.f);
            *(float4*)(g_seq + (size_t)n * 256 + slot * 64 + q * 4) = tac;
            __syncwarp();
        }
        gridbar(sense, &g_barcnt2, &g_barsense2);
    }
}

// ================= fused transformer + mean + classifier (R8 proven, unchanged) =================
#define SSTR 68
#define FSTR 136
#define WSCR 1168
#define FW   20
#define FT   640

__global__ void __launch_bounds__(FT, 1) k_former(
    const float* __restrict__ W1_g,   const float* __restrict__ b1_g,
    const float* __restrict__ W2_g,   const float* __restrict__ b2_g,
    const float* __restrict__ ln1w_g, const float* __restrict__ ln1b_g,
    const float* __restrict__ ln2w_g, const float* __restrict__ ln2b_g,
    const float* __restrict__ Wcls_g, const float* __restrict__ bcls_g,
    float* __restrict__ out)
{
    extern __shared__ float sm[];
    float* MtS   = sm;
    float* WvoS  = MtS + 4096;
    float* W1S   = WvoS + 4096;
    float* W2S   = W1S + 8192;
    float* WclsS = W2S + 8192;
    float* p2S   = WclsS + 2560;
    float* bvoS  = p2S + 64;
    float* b1S   = bvoS + 64;
    float* b2S   = b1S + 128;
    float* bclsS = b2S + 64;
    float* ln1wS = bclsS + 40;
    float* ln1bS = ln1wS + 64;
    float* ln2wS = ln1bS + 64;
    float* ln2bS = ln2wS + 64;
    float* scratch = ln2bS + 64;

    int tid = threadIdx.x;
    for (int i = tid; i < 4096; i += FT) { MtS[i] = g_Mt[i]; WvoS[i] = g_Wvo[i]; }
    for (int i = tid; i < 8192; i += FT) { int j = i & 127, k = i >> 7; W1S[k * 128 + j] = W1_g[j * 64 + k]; }
    for (int i = tid; i < 8192; i += FT) { int j = i & 63,  k = i >> 6; W2S[k * 64 + j]  = W2_g[j * 128 + k]; }
    for (int i = tid; i < 2560; i += FT) { int j = i % 40,  k = i / 40; WclsS[k * 40 + j] = Wcls_g[j * 64 + k]; }
    if (tid < 64) {
        p2S[tid] = g_p2[tid]; bvoS[tid] = g_bvo[tid]; b2S[tid] = b2_g[tid];
        ln1wS[tid] = ln1w_g[tid]; ln1bS[tid] = ln1b_g[tid];
        ln2wS[tid] = ln2w_g[tid]; ln2bS[tid] = ln2b_g[tid];
    }
    if (tid >= 64 && tid < 192) b1S[tid - 64] = b1_g[tid - 64];
    if (tid >= 192 && tid < 232) bclsS[tid - 192] = bcls_g[tid - 192];
    __syncthreads();

    int warp = tid >> 5, l = tid & 31;
    float* s   = scratch + warp * WSCR;
    float* z   = s + 272;
    float* b2f = z + 272;
    float* sc  = b2f + 544;
    float* hb  = sc + 16;
    const int t = l >> 3, g = l & 7;
    float* srow = s + t * SSTR;
    const int c1 = 4 * g, c2 = 32 + 4 * g;

    for (int n = blockIdx.x * FW + warp; n < Nn; n += gridDim.x * FW) {
        {
            const float4* sp = (const float4*)(g_seq + (size_t)n * 256);
            int t0 = l >> 4, m = l & 15;
            float4 v0 = sp[l], v1 = sp[l + 32];
            ((float4*)(s + t0 * SSTR))[m] = v0;
            ((float4*)(s + (t0 + 2) * SSTR))[m] = v1;
        }
        __syncwarp();

        // ---- z_t = M s_t (f32x2) ----
        {
            ull p0 = 0, p1 = 0, p2 = 0, p3 = 0;
            #pragma unroll 4
            for (int k4 = 0; k4 < 16; k4++) {
                float4 xv = ((const float4*)srow)[k4];
                #pragma unroll
                for (int kk = 0; kk < 4; kk++) {
                    const float* wrow = MtS + (k4 * 4 + kk) * 64;
                    ulonglong2 wa = *(const ulonglong2*)(wrow + c1);
                    ulonglong2 wb = *(const ulonglong2*)(wrow + c2);
                    float xk = kk == 0 ? xv.x : kk == 1 ? xv.y : kk == 2 ? xv.z : xv.w;
                    ull x2 = bcast2(xk);
                    ffma2(p0, x2, wa.x); ffma2(p1, x2, wa.y);
                    ffma2(p2, x2, wb.x); ffma2(p3, x2, wb.y);
                }
            }
            *(ulonglong2*)(z + t * SSTR + c1) = make_ulonglong2(p0, p1);
            *(ulonglong2*)(z + t * SSTR + c2) = make_ulonglong2(p2, p3);
        }
        __syncwarp();

        // ---- scores + softmax ----
        if (l < 16) {
            int ss = l >> 2, tt = l & 3;
            const float4* ap = (const float4*)(s + ss * SSTR);
            const float4* zp = (const float4*)(z + tt * SSTR);
            const float4* bp = (const float4*)(s + tt * SSTR);
            const float4* pp = (const float4*)p2S;
            float d = 0.f;
            #pragma unroll 4
            for (int k4 = 0; k4 < 16; k4++) {
                float4 a = ap[k4], zz = zp[k4], bq = bp[k4], p = pp[k4];
                d += a.x * zz.x + a.y * zz.y + a.z * zz.z + a.w * zz.w;
                d += p.x * bq.x + p.y * bq.y + p.z * bq.z + p.w * bq.w;
            }
            sc[l] = d * 0.125f;
        }
        __syncwarp();
        if (l < 4) {
            float s0 = sc[l*4], s1 = sc[l*4+1], s2 = sc[l*4+2], s3 = sc[l*4+3];
            float m = fmaxf(fmaxf(s0, s1), fmaxf(s2, s3));
            float e0 = __expf(s0 - m), e1 = __expf(s1 - m), e2 = __expf(s2 - m), e3 = __expf(s3 - m);
            float inv = 1.f / (e0 + e1 + e2 + e3);
            sc[l*4] = e0*inv; sc[l*4+1] = e1*inv; sc[l*4+2] = e2*inv; sc[l*4+3] = e3*inv;
        }
        __syncwarp();

        // ---- m_t = sum_c P[t,c] s_c ----
        {
            float w0 = sc[t*4], w1 = sc[t*4+1], w2 = sc[t*4+2], w3 = sc[t*4+3];
            #pragma unroll
            for (int h = 0; h < 2; h++) {
                int c = h == 0 ? c1 : c2;
                float4 s0 = *(const float4*)(s + c);
                float4 s1 = *(const float4*)(s + SSTR + c);
                float4 s2 = *(const float4*)(s + 2 * SSTR + c);
                float4 s3 = *(const float4*)(s + 3 * SSTR + c);
                float4 r;
                r.x = w0*s0.x + w1*s1.x + w2*s2.x + w3*s3.x;
                r.y = w0*s0.y + w1*s1.y + w2*s2.y + w3*s3.y;
                r.z = w0*s0.z + w1*s1.z + w2*s2.z + w3*s3.z;
                r.w = w0*s0.w + w1*s1.w + w2*s2.w + w3*s3.w;
                *(float4*)(b2f + t * FSTR + c) = r;
            }
        }
        __syncwarp();

        // ---- out = Wvo m + bvo, residual, LN1 (f32x2) ----
        {
            ulonglong2 bv1 = *(const ulonglong2*)(bvoS + c1);
            ulonglong2 bv2 = *(const ulonglong2*)(bvoS + c2);
            ull p0 = bv1.x, p1 = bv1.y, p2 = bv2.x, p3 = bv2.y;
            const float* arow = b2f + t * FSTR;
            #pragma unroll 4
            for (int k4 = 0; k4 < 16; k4++) {
                float4 av = ((const float4*)arow)[k4];
                #pragma unroll
                for (int kk = 0; kk < 4; kk++) {
                    const float* wrow = WvoS + (k4 * 4 + kk) * 64;
                    ulonglong2 wa = *(const ulonglong2*)(wrow + c1);
                    ulonglong2 wb = *(const ulonglong2*)(wrow + c2);
                    float ak = kk == 0 ? av.x : kk == 1 ? av.y : kk == 2 ? av.z : av.w;
                    ull a2 = bcast2(ak);
                    ffma2(p0, a2, wa.x); ffma2(p1, a2, wa.y);
                    ffma2(p2, a2, wb.x); ffma2(p3, a2, wb.y);
                }
            }
            float2 q0 = unpk(p0), q1 = unpk(p1), q2 = unpk(p2), q3 = unpk(p3);
            float4 rs0 = *(const float4*)(srow + c1);
            float4 rs1 = *(const float4*)(srow + c2);
            float r[8];
            r[0] = q0.x + rs0.x; r[1] = q0.y + rs0.y; r[2] = q1.x + rs0.z; r[3] = q1.y + rs0.w;
            r[4] = q2.x + rs1.x; r[5] = q2.y + rs1.y; r[6] = q3.x + rs1.z; r[7] = q3.y + rs1.w;
            float sum = r[0]+r[1]+r[2]+r[3]+r[4]+r[5]+r[6]+r[7];
            sum += __shfl_xor_sync(0xffffffffu, sum, 1);
            sum += __shfl_xor_sync(0xffffffffu, sum, 2);
            sum += __shfl_xor_sync(0xffffffffu, sum, 4);
            float mean = sum * 0.015625f;
            float sq = 0.f;
            #pragma unroll
            for (int i = 0; i < 8; i++) { float dd = r[i] - mean; sq = fmaf(dd, dd, sq); }
            sq += __shfl_xor_sync(0xffffffffu, sq, 1);
            sq += __shfl_xor_sync(0xffffffffu, sq, 2);
            sq += __shfl_xor_sync(0xffffffffu, sq, 4);
            float inv = rsqrtf(sq * 0.015625f + 1e-5f);
            float4 wA = *(const float4*)(ln1wS + c1), wB = *(const float4*)(ln1wS + c2);
            float4 bA = *(const float4*)(ln1bS + c1), bB = *(const float4*)(ln1bS + c2);
            float4 o0, o1;
            o0.x = (r[0]-mean)*inv*wA.x + bA.x; o0.y = (r[1]-mean)*inv*wA.y + bA.y;
            o0.z = (r[2]-mean)*inv*wA.z + bA.z; o0.w = (r[3]-mean)*inv*wA.w + bA.w;
            o1.x = (r[4]-mean)*inv*wB.x + bB.x; o1.y = (r[5]-mean)*inv*wB.y + bB.y;
            o1.z = (r[6]-mean)*inv*wB.z + bB.z; o1.w = (r[7]-mean)*inv*wB.w + bB.w;
            *(float4*)(srow + c1) = o0;
            *(float4*)(srow + c2) = o1;
        }
        __syncwarp();

        // ---- FF1 + exact gelu (f32x2) ----
        {
            ull q[8];
            #pragma unroll
            for (int i = 0; i < 4; i++) {
                ulonglong2 bi = *(const ulonglong2*)(b1S + 32 * i + c1);
                q[2*i] = bi.x; q[2*i+1] = bi.y;
            }
            #pragma unroll 2
            for (int k4 = 0; k4 < 16; k4++) {
                float4 xv = ((const float4*)srow)[k4];
                #pragma unroll
                for (int kk = 0; kk < 4; kk++) {
                    const float* wrow = W1S + (k4 * 4 + kk) * 128;
                    float xk = kk == 0 ? xv.x : kk == 1 ? xv.y : kk == 2 ? xv.z : xv.w;
                    ull x2 = bcast2(xk);
                    #pragma unroll
                    for (int i = 0; i < 4; i++) {
                        ulonglong2 w = *(const ulonglong2*)(wrow + 32 * i + c1);
                        ffma2(q[2*i], x2, w.x);
                        ffma2(q[2*i+1], x2, w.y);
                    }
                }
            }
            float* gp = b2f + t * FSTR;
            #pragma unroll
            for (int i = 0; i < 4; i++) {
                float2 u0 = unpk(q[2*i]), u1 = unpk(q[2*i+1]);
                float4 v;
                v.x = 0.5f * u0.x * (1.0f + erff(u0.x * 0.70710678118f));
                v.y = 0.5f * u0.y * (1.0f + erff(u0.y * 0.70710678118f));
                v.z = 0.5f * u1.x * (1.0f + erff(u1.x * 0.70710678118f));
                v.w = 0.5f * u1.y * (1.0f + erff(u1.y * 0.70710678118f));
                *(float4*)(gp + 32 * i + c1) = v;
            }
        }
        __syncwarp();

        // ---- FF2 + residual + LN2 + token mean (f32x2) ----
        {
            ulonglong2 bv1 = *(const ulonglong2*)(b2S + c1);
            ulonglong2 bv2 = *(const ulonglong2*)(b2S + c2);
            ull p0 = bv1.x, p1 = bv1.y, p2 = bv2.x, p3 = bv2.y;
            const float* grow = b2f + t * FSTR;
            #pragma unroll 2
            for (int k4 = 0; k4 < 32; k4++) {
                float4 gv = ((const float4*)grow)[k4];
                #pragma unroll
                for (int kk = 0; kk < 4; kk++) {
                    const float* wrow = W2S + (k4 * 4 + kk) * 64;
                    ulonglong2 wa = *(const ulonglong2*)(wrow + c1);
                    ulonglong2 wb = *(const ulonglong2*)(wrow + c2);
                    float gk = kk == 0 ? gv.x : kk == 1 ? gv.y : kk == 2 ? gv.z : gv.w;
                    ull g2 = bcast2(gk);
                    ffma2(p0, g2, wa.x); ffma2(p1, g2, wa.y);
                    ffma2(p2, g2, wb.x); ffma2(p3, g2, wb.y);
                }
            }
            float2 q0 = unpk(p0), q1 = unpk(p1), q2 = unpk(p2), q3 = unpk(p3);
            float4 rs0 = *(const float4*)(srow + c1);
            float4 rs1 = *(const float4*)(srow + c2);
            float f[8];
            f[0] = q0.x + rs0.x; f[1] = q0.y + rs0.y; f[2] = q1.x + rs0.z; f[3] = q1.y + rs0.w;
            f[4] = q2.x + rs1.x; f[5] = q2.y + rs1.y; f[6] = q3.x + rs1.z; f[7] = q3.y + rs1.w;
            float sum = f[0]+f[1]+f[2]+f[3]+f[4]+f[5]+f[6]+f[7];
            sum += __shfl_xor_sync(0xffffffffu, sum, 1);
            sum += __shfl_xor_sync(0xffffffffu, sum, 2);
            sum += __shfl_xor_sync(0xffffffffu, sum, 4);
            float mean = sum * 0.015625f;
            float sq = 0.f;
            #pragma unroll
            for (int i = 0; i < 8; i++) { float dd = f[i] - mean; sq = fmaf(dd, dd, sq); }
            sq += __shfl_xor_sync(0xffffffffu, sq, 1);
            sq += __shfl_xor_sync(0xffffffffu, sq, 2);
            sq += __shfl_xor_sync(0xffffffffu, sq, 4);
            float inv = rsqrtf(sq * 0.015625f + 1e-5f);
            float x2v[8];
            #pragma unroll
            for (int i = 0; i < 8; i++) {
                int j = (i < 4) ? (c1 + i) : (c2 + i - 4);
                x2v[i] = (f[i] - mean) * inv * ln2wS[j] + ln2bS[j];
            }
            #pragma unroll
            for (int i = 0; i < 8; i++) {
                float v = x2v[i];
                v += __shfl_xor_sync(0xffffffffu, v, 8);
                v += __shfl_xor_sync(0xffffffffu, v, 16);
                x2v[i] = v * 0.25f;
            }
            if (t == 0) {
                *(float4*)(hb + c1) = make_float4(x2v[0], x2v[1], x2v[2], x2v[3]);
                *(float4*)(hb + c2) = make_float4(x2v[4], x2v[5], x2v[6], x2v[7]);
            }
        }
        __syncwarp();

        // ---- classifier ----
        {
            float o0 = bclsS[l];
            float o1 = bclsS[32 + g];
            #pragma unroll 4
            for (int k4 = 0; k4 < 16; k4++) {
                float4 hv = ((const float4*)hb)[k4];
                const float* wr = WclsS + k4 * 160;
                o0 = fmaf(hv.x, wr[l], o0);        o1 = fmaf(hv.x, wr[32 + g], o1);
                o0 = fmaf(hv.y, wr[40 + l], o0);   o1 = fmaf(hv.y, wr[72 + g], o1);
                o0 = fmaf(hv.z, wr[80 + l], o0);   o1 = fmaf(hv.z, wr[112 + g], o1);
                o0 = fmaf(hv.w, wr[120 + l], o0);  o1 = fmaf(hv.w, wr[152 + g], o1);
            }
            out[(size_t)n * 40 + l] = o0;
            if (l < 8) out[(size_t)n * 40 + 32 + l] = o1;
        }
        __syncwarp();
    }
}

extern "C" void kernel_launch(void* const* d_in, const int* in_sizes, int n_in,
                              void* d_out, int out_size) {
    const float* x     = (const float*)d_in[0];
    const int*   ei    = (const int*)d_in[1];
    const float* W_in  = (const float*)d_in[2];
    const float* b_in  = (const float*)d_in[3];
    const float* sg_W  = (const float*)d_in[4];
    const float* sg_b  = (const float*)d_in[5];
    const float* inW   = (const float*)d_in[6];
    const float* inb   = (const float*)d_in[7];
    const float* Wout  = (const float*)d_in[8];
    const float* bout  = (const float*)d_in[9];
    const float* W1    = (const float*)d_in[10];
    const float* b1    = (const float*)d_in[11];
    const float* W2    = (const float*)d_in[12];
    const float* b2    = (const float*)d_in[13];
    const float* ln1w  = (const float*)d_in[14];
    const float* ln1b  = (const float*)d_in[15];
    const float* ln2w  = (const float*)d_in[16];
    const float* ln2b  = (const float*)d_in[17];
    const float* Wcls  = (const float*)d_in[18];
    const float* bcls  = (const float*)d_in[19];
    float* out = (float*)d_out;

    cudaFuncSetAttribute(k_in_linear, cudaFuncAttributeMaxDynamicSharedMemorySize, 99584);
    cudaFuncSetAttribute(k_former,    cudaFuncAttributeMaxDynamicSharedMemorySize, 204448);

    // 1: CSR build + folded matrices (persistent)
    k_build<<<148, 256>>>(ei, ei + Ee, inW, inb, Wout, bout);
    // 2: h0 + seq slot 0
    k_in_linear<<<592, 256, 99584>>>(x, W_in, b_in);
    // 3: all 3 hops, persistent with grid barriers
    k_prop_all<<<592, 256>>>(sg_W, sg_b);
    // 4: fused transformer + pooling + classifier  (launch #4 -> profiled)
    k_former<<<148, FT, 204448>>>(W1, b1, W2, b2, ln1w, ln1b, ln2w, ln2b, Wcls, bcls, out);
}

// round 11
// speedup vs baseline: 1.4170x; 1.4170x over previous
#include <cuda_runtime.h>
#include <math.h>

#define Nn   100000
#define Ee   1600000
#define NH   (Nn * 64)
#define CHUNK 676   // ceil(100000/148)

// ---- persistent device scratch ----
__device__ float g_dinv[Nn];
__device__ int   g_cnt[Nn];
__device__ int   g_off[Nn];
__device__ int   g_cur[Nn];
__device__ int   g_bsum[256];
__device__ int2  g_csr[Ee];
__device__ float g_hb[3][NH];
__device__ float g_seq[(size_t)Nn * 256];
__device__ float g_Mt[4096];
__device__ float g_Wvo[4096];
__device__ float g_p2[64];
__device__ float g_bvo[64];

// ---- grid-wide barriers ----
__device__ unsigned g_barcnt1 = 0;
__device__ volatile unsigned g_barsense1 = 0;
__device__ unsigned g_barcnt2 = 0;
__device__ volatile unsigned g_barsense2 = 0;

__device__ __forceinline__ void gridbar(unsigned& sense, unsigned* cnt,
                                        volatile unsigned* gsense) {
    __threadfence();
    __syncthreads();
    if (threadIdx.x == 0) {
        sense ^= 1u;
        unsigned old = atomicAdd(cnt, 1u);
        if (old == gridDim.x - 1) {
            atomicExch(cnt, 0u);
            __threadfence();
            *gsense = sense;
        } else {
            while (*gsense != sense) { }
        }
    }
    __syncthreads();
}

// ================= single-kernel CSR build + dinv + folded matrices =================
__global__ void __launch_bounds__(256) k_build(
    const int* __restrict__ src, const int* __restrict__ dst,
    const float* __restrict__ inW, const float* __restrict__ inb,
    const float* __restrict__ WoutG, const float* __restrict__ boutG) {
    __shared__ int part[256];
    int tid = threadIdx.x, cta = blockIdx.x;
    int gs = gridDim.x * 256;
    unsigned sense = g_barsense1;

    for (int e = cta * 256 + tid; e < 4096; e += gs) {
        int bcol = e >> 6, a = e & 63;
        float m = 0.f, wv = 0.f;
        for (int j = 0; j < 64; j++) {
            m  = fmaf(__ldg(inW + j * 64 + a),   __ldg(inW + (64 + j) * 64 + bcol), m);
            wv = fmaf(__ldg(WoutG + a * 64 + j), __ldg(inW + (128 + j) * 64 + bcol), wv);
        }
        g_Mt[e] = m;
        g_Wvo[e] = wv;
    }
    if (cta == 147) {
        if (tid < 64) {
            float p = 0.f;
            for (int j = 0; j < 64; j++) p = fmaf(__ldg(inb + j), __ldg(inW + (64 + j) * 64 + tid), p);
            g_p2[tid] = p;
        } else if (tid < 128) {
            int a = tid - 64;
            float bv = __ldg(boutG + a);
            for (int j = 0; j < 64; j++) bv = fmaf(__ldg(WoutG + a * 64 + j), __ldg(inb + 128 + j), bv);
            g_bvo[a] = bv;
        }
    }
    for (int i = cta * 256 + tid; i < Nn; i += gs) g_cnt[i] = 0;
    gridbar(sense, &g_barcnt1, &g_barsense1);
    for (int e = cta * 256 + tid; e < Ee; e += gs) atomicAdd(&g_cnt[dst[e]], 1);
    gridbar(sense, &g_barcnt1, &g_barsense1);
    int base = cta * CHUNK;
    int lim = min(base + CHUNK, Nn);
    int i0 = base + tid * 3;
    int c0 = (i0     < lim) ? g_cnt[i0]     : 0;
    int c1 = (i0 + 1 < lim) ? g_cnt[i0 + 1] : 0;
    int c2 = (i0 + 2 < lim) ? g_cnt[i0 + 2] : 0;
    int tsum = c0 + c1 + c2;
    part[tid] = tsum;
    __syncthreads();
    for (int off = 1; off < 256; off <<= 1) {
        int v = (tid >= off) ? part[tid - off] : 0;
        __syncthreads();
        if (tid >= off) part[tid] += v;
        __syncthreads();
    }
    if (tid == 255) g_bsum[cta] = part[255];
    gridbar(sense, &g_barcnt1, &g_barsense1);
    if (cta == 0 && tid == 0) {
        int acc = 0;
        for (int b = 0; b < (int)gridDim.x; b++) { int t = g_bsum[b]; g_bsum[b] = acc; acc += t; }
    }
    gridbar(sense, &g_barcnt1, &g_barsense1);
    {
        int ctaoff = g_bsum[cta];
        int texcl = ctaoff + part[tid] - tsum;
        if (i0 < lim) {
            g_off[i0] = texcl; g_cur[i0] = texcl;
            g_dinv[i0] = rsqrtf((float)c0 + 1.0f);
        }
        if (i0 + 1 < lim) {
            int ex = texcl + c0;
            g_off[i0 + 1] = ex; g_cur[i0 + 1] = ex;
            g_dinv[i0 + 1] = rsqrtf((float)c1 + 1.0f);
        }
        if (i0 + 2 < lim) {
            int ex = texcl + c0 + c1;
            g_off[i0 + 2] = ex; g_cur[i0 + 2] = ex;
            g_dinv[i0 + 2] = rsqrtf((float)c2 + 1.0f);
        }
    }
    gridbar(sense, &g_barcnt1, &g_barsense1);
    for (int e = cta * 256 + tid; e < Ee; e += gs) {
        int s = src[e], d = dst[e];
        int pos = atomicAdd(&g_cur[d], 1);
        g_csr[pos] = make_int2(s, __float_as_int(g_dinv[s]));
    }
}

// ================= h0 = relu(x @ W_in^T + b_in) =================
__global__ void k_in_linear(const float* __restrict__ x, const float* __restrict__ W,
                            const float* __restrict__ b) {
    extern __shared__ float sm[];
    float* Ws = sm;                 // [64][260]
    float* bb = Ws + 64 * 260;
    float* xb = bb + 64;
    int tid = threadIdx.x;
    for (int i = tid; i < 64 * 64; i += 256) {
        int j = i >> 6, q = i & 63;
        ((float4*)(Ws + j * 260))[q] = ((const float4*)(W + j * 256))[q];
    }
    if (tid < 64) bb[tid] = b[tid];
    __syncthreads();
    int warp = tid >> 5, l = tid & 31;
    float* xw = xb + warp * 1024;
    const float* w0p = Ws + l * 260;
    const float* w1p = Ws + (l + 32) * 260;
    for (int grp = blockIdx.x * 8 + warp; grp < 25000; grp += gridDim.x * 8) {
        int row0 = grp * 4;
        const float4* xg = (const float4*)(x + (size_t)row0 * 256);
        #pragma unroll
        for (int r = 0; r < 4; r++) {
            ((float4*)xw)[r * 64 + l]      = xg[r * 64 + l];
            ((float4*)xw)[r * 64 + l + 32] = xg[r * 64 + l + 32];
        }
        __syncwarp();
        float acc0[4], acc1[4];
        #pragma unroll
        for (int r = 0; r < 4; r++) { acc0[r] = bb[l]; acc1[r] = bb[l + 32]; }
        #pragma unroll 4
        for (int k4 = 0; k4 < 64; k4++) {
            float4 wa = ((const float4*)w0p)[k4];
            float4 wb = ((const float4*)w1p)[k4];
            #pragma unroll
            for (int r = 0; r < 4; r++) {
                float4 xv = ((const float4*)(xw + r * 256))[k4];
                acc0[r] = fmaf(xv.x, wa.x, acc0[r]);
                acc0[r] = fmaf(xv.y, wa.y, acc0[r]);
                acc0[r] = fmaf(xv.z, wa.z, acc0[r]);
                acc0[r] = fmaf(xv.w, wa.w, acc0[r]);
                acc1[r] = fmaf(xv.x, wb.x, acc1[r]);
                acc1[r] = fmaf(xv.y, wb.y, acc1[r]);
                acc1[r] = fmaf(xv.z, wb.z, acc1[r]);
                acc1[r] = fmaf(xv.w, wb.w, acc1[r]);
            }
        }
        #pragma unroll
        for (int r = 0; r < 4; r++) {
            float a0 = fmaxf(acc0[r], 0.f), a1 = fmaxf(acc1[r], 0.f);
            size_t row = row0 + r;
            g_hb[0][row * 64 + l]      = a0;
            g_hb[0][row * 64 + l + 32] = a1;
            g_seq[row * 256 + l]       = a0;
            g_seq[row * 256 + l + 32]  = a1;
        }
        __syncwarp();
    }
}

// ================= fused 3-hop gather-propagate + token linears (persistent) =================
__global__ void __launch_bounds__(256, 4) k_prop_all(const float* __restrict__ sgW,
                                                     const float* __restrict__ sgb) {
    __shared__ float Wt[4096];
    __shared__ float bb[64];
    __shared__ float pbuf[8][2][64];
    __shared__ int2  ebuf[8][32];
    int tid = threadIdx.x;
    int warp = tid >> 5, l = tid & 31;
    int half = l >> 4, q = l & 15;
    int2* eb = ebuf[warp];
    unsigned sense = g_barsense2;

    const int ib[3] = {0, 1, 2};
    const int ob[3] = {1, 2, 1};

    for (int hop = 0; hop < 3; hop++) {
        const float* W = sgW + hop * 4096;
        for (int i = tid; i < 4096; i += 256) {
            int k = i >> 6, j = i & 63;
            Wt[i] = W[j * 64 + k];
        }
        if (tid < 64) bb[tid] = sgb[hop * 64 + tid];
        __syncthreads();

        const float* hin = g_hb[ib[hop]];
        float* hout = g_hb[ob[hop]];
        int slot = hop + 1;

        for (int pair = blockIdx.x * 8 + warp; pair < 50000; pair += gridDim.x * 8) {
            int n = pair * 2 + half;
            int beg = g_off[n], cnt = g_cnt[n];
            float dn = g_dinv[n];
            float4 acc = ((const float4*)(hin + (size_t)n * 64))[q];
            acc.x *= dn; acc.y *= dn; acc.z *= dn; acc.w *= dn;
            int cntO = __shfl_xor_sync(0xffffffffu, cnt, 16);
            int cmax = cnt > cntO ? cnt : cntO;
            for (int chunk = 0; chunk < cmax; chunk += 16) {
                if (chunk + q < cnt) eb[l] = __ldg(&g_csr[beg + chunk + q]);
                __syncwarp();
                int m = min(16, cnt - chunk);
                int base = half * 16;
                int i = 0;
                for (; i + 4 <= m; i += 4) {
                    float4 v[4]; float w[4];
                    #pragma unroll
                    for (int u = 0; u < 4; u++) {
                        int2 e = eb[base + i + u];
                        v[u] = __ldg((const float4*)(hin + (size_t)e.x * 64) + q);
                        w[u] = __int_as_float(e.y);
                    }
                    #pragma unroll
                    for (int u = 0; u < 4; u++) {
                        acc.x = fmaf(w[u], v[u].x, acc.x);
                        acc.y = fmaf(w[u], v[u].y, acc.y);
                        acc.z = fmaf(w[u], v[u].z, acc.z);
                        acc.w = fmaf(w[u], v[u].w, acc.w);
                    }
                }
                for (; i < m; i++) {
                    int2 e = eb[base + i];
                    float4 v0 = __ldg((const float4*)(hin + (size_t)e.x * 64) + q);
                    float w0 = __int_as_float(e.y);
                    acc.x = fmaf(w0, v0.x, acc.x);
                    acc.y = fmaf(w0, v0.y, acc.y);
                    acc.z = fmaf(w0, v0.z, acc.z);
                    acc.w = fmaf(w0, v0.w, acc.w);
                }
                __syncwarp();
            }
            acc.x *= dn; acc.y *= dn; acc.z *= dn; acc.w *= dn;
            ((float4*)(hout + (size_t)n * 64))[q] = acc;
            ((float4*)pbuf[warp][half])[q] = acc;
            __syncwarp();
            const float* pw = pbuf[warp][half];
            float4 tac = *(const float4*)(bb + q * 4);
            #pragma unroll 4
            for (int k4 = 0; k4 < 16; k4++) {
                float4 xv = ((const float4*)pw)[k4];
                #pragma unroll
                for (int kk = 0; kk < 4; kk++) {
                    float4 w = *(const float4*)(Wt + (k4 * 4 + kk) * 64 + q * 4);
                    float xk = kk == 0 ? xv.x : kk == 1 ? xv.y : kk == 2 ? xv.z : xv.w;
                    tac.x = fmaf(xk, w.x, tac.x);
                    tac.y = fmaf(xk, w.y, tac.y);
                    tac.z = fmaf(xk, w.z, tac.z);
                    tac.w = fmaf(xk, w.w, tac.w);
                }
            }
            tac.x = fmaxf(tac.x, 0.f); tac.y = fmaxf(tac.y, 0.f);
            tac.z = fmaxf(tac.z, 0.f); tac.w = fmaxf(tac.w, 0.f);
            *(float4*)(g_seq + (size_t)n * 256 + slot * 64 + q * 4) = tac;
            __syncwarp();
        }
        gridbar(sense, &g_barcnt2, &g_barsense2);
    }
}

// ================= fused transformer: TWO nodes per warp (shared weight loads) =================
#define SSTR 68
#define FSTR 136
#define NODE 896    // per-node scratch: s 272 | b2f 544 (z aliased inside) | sc 16 | hb 64
#define FW   16
#define FT   512

__global__ void __launch_bounds__(FT, 1) k_former(
    const float* __restrict__ W1_g,   const float* __restrict__ b1_g,
    const float* __restrict__ W2_g,   const float* __restrict__ b2_g,
    const float* __restrict__ ln1w_g, const float* __restrict__ ln1b_g,
    const float* __restrict__ ln2w_g, const float* __restrict__ ln2b_g,
    const float* __restrict__ Wcls_g, const float* __restrict__ bcls_g,
    float* __restrict__ out)
{
    extern __shared__ float sm[];
    float* MtS   = sm;
    float* WvoS  = MtS + 4096;
    float* W1S   = WvoS + 4096;
    float* W2S   = W1S + 8192;
    float* WclsS = W2S + 8192;
    float* p2S   = WclsS + 2560;
    float* bvoS  = p2S + 64;
    float* b1S   = bvoS + 64;
    float* b2S   = b1S + 128;
    float* bclsS = b2S + 64;
    float* ln1wS = bclsS + 40;
    float* ln1bS = ln1wS + 64;
    float* ln2wS = ln1bS + 64;
    float* ln2bS = ln2wS + 64;
    float* scratch = ln2bS + 64;    // FW * 2 * NODE

    int tid = threadIdx.x;
    for (int i = tid; i < 4096; i += FT) { MtS[i] = g_Mt[i]; WvoS[i] = g_Wvo[i]; }
    for (int i = tid; i < 8192; i += FT) { int j = i & 127, k = i >> 7; W1S[k * 128 + j] = W1_g[j * 64 + k]; }
    for (int i = tid; i < 8192; i += FT) { int j = i & 63,  k = i >> 6; W2S[k * 64 + j]  = W2_g[j * 128 + k]; }
    for (int i = tid; i < 2560; i += FT) { int j = i % 40,  k = i / 40; WclsS[k * 40 + j] = Wcls_g[j * 64 + k]; }
    if (tid < 64) {
        p2S[tid] = g_p2[tid]; bvoS[tid] = g_bvo[tid]; b2S[tid] = b2_g[tid];
        ln1wS[tid] = ln1w_g[tid]; ln1bS[tid] = ln1b_g[tid];
        ln2wS[tid] = ln2w_g[tid]; ln2bS[tid] = ln2b_g[tid];
    }
    if (tid >= 64 && tid < 192) b1S[tid - 64] = b1_g[tid - 64];
    if (tid >= 192 && tid < 232) bclsS[tid - 192] = bcls_g[tid - 192];
    __syncthreads();

    int warp = tid >> 5, l = tid & 31;
    float* nA = scratch + warp * (2 * NODE);
    float* nB = nA + NODE;
    float* sA = nA;              float* sB = nB;
    float* zA = nA + 272;        float* zB = nB + 272;   // aliased into b2f region
    float* fA = nA + 272;        float* fB = nB + 272;
    float* scAp = nA + 816;      float* scBp = nB + 816;
    float* hbA = nA + 832;       float* hbB = nB + 832;
    const int t = l >> 3, g = l & 7;
    float* srA = sA + t * SSTR;
    float* srB = sB + t * SSTR;
    const int c1 = 4 * g, c2 = 32 + 4 * g;

    for (int p = blockIdx.x * FW + warp; p < 50000; p += gridDim.x * FW) {
        int n0 = 2 * p;
        // ---- load seq for both nodes ----
        {
            const float4* spA = (const float4*)(g_seq + (size_t)n0 * 256);
            const float4* spB = spA + 64;
            int t0 = l >> 4, m = l & 15;
            ((float4*)(sA + t0 * SSTR))[m]       = spA[l];
            ((float4*)(sA + (t0 + 2) * SSTR))[m] = spA[l + 32];
            ((float4*)(sB + t0 * SSTR))[m]       = spB[l];
            ((float4*)(sB + (t0 + 2) * SSTR))[m] = spB[l + 32];
        }
        __syncwarp();

        // ---- z = M s (dual) ----
        {
            float4 a0A = make_float4(0.f,0.f,0.f,0.f), a1A = a0A, a0B = a0A, a1B = a0A;
            for (int k4 = 0; k4 < 16; k4++) {
                float4 xvA = ((const float4*)srA)[k4];
                float4 xvB = ((const float4*)srB)[k4];
                #pragma unroll
                for (int kk = 0; kk < 4; kk++) {
                    const float* wrow = MtS + (k4 * 4 + kk) * 64;
                    float4 wA = *(const float4*)(wrow + c1);
                    float4 wB = *(const float4*)(wrow + c2);
                    float xa = kk == 0 ? xvA.x : kk == 1 ? xvA.y : kk == 2 ? xvA.z : xvA.w;
                    float xb = kk == 0 ? xvB.x : kk == 1 ? xvB.y : kk == 2 ? xvB.z : xvB.w;
                    a0A.x = fmaf(xa, wA.x, a0A.x); a0A.y = fmaf(xa, wA.y, a0A.y);
                    a0A.z = fmaf(xa, wA.z, a0A.z); a0A.w = fmaf(xa, wA.w, a0A.w);
                    a1A.x = fmaf(xa, wB.x, a1A.x); a1A.y = fmaf(xa, wB.y, a1A.y);
                    a1A.z = fmaf(xa, wB.z, a1A.z); a1A.w = fmaf(xa, wB.w, a1A.w);
                    a0B.x = fmaf(xb, wA.x, a0B.x); a0B.y = fmaf(xb, wA.y, a0B.y);
                    a0B.z = fmaf(xb, wA.z, a0B.z); a0B.w = fmaf(xb, wA.w, a0B.w);
                    a1B.x = fmaf(xb, wB.x, a1B.x); a1B.y = fmaf(xb, wB.y, a1B.y);
                    a1B.z = fmaf(xb, wB.z, a1B.z); a1B.w = fmaf(xb, wB.w, a1B.w);
                }
            }
            *(float4*)(zA + t * SSTR + c1) = a0A;
            *(float4*)(zA + t * SSTR + c2) = a1A;
            *(float4*)(zB + t * SSTR + c1) = a0B;
            *(float4*)(zB + t * SSTR + c2) = a1B;
        }
        __syncwarp();

        // ---- scores: 16 lanes per node ----
        {
            int nd = l >> 4, idx = l & 15, ss = idx >> 2, tt = idx & 3;
            const float* sbase = nd ? sB : sA;
            const float* zbase = nd ? zB : zA;
            float* scp = nd ? scBp : scAp;
            const float4* ap = (const float4*)(sbase + ss * SSTR);
            const float4* zp = (const float4*)(zbase + tt * SSTR);
            const float4* bp = (const float4*)(sbase + tt * SSTR);
            const float4* pp = (const float4*)p2S;
            float d = 0.f;
            #pragma unroll 4
            for (int k4 = 0; k4 < 16; k4++) {
                float4 a = ap[k4], zz = zp[k4], bq = bp[k4], pv = pp[k4];
                d += a.x * zz.x + a.y * zz.y + a.z * zz.z + a.w * zz.w;
                d += pv.x * bq.x + pv.y * bq.y + pv.z * bq.z + pv.w * bq.w;
            }
            scp[idx] = d * 0.125f;
        }
        __syncwarp();
        if ((l & 15) < 4) {
            float* scp = (l >> 4) ? scBp : scAp;
            int r = (l & 15) * 4;
            float s0 = scp[r], s1 = scp[r+1], s2 = scp[r+2], s3 = scp[r+3];
            float m = fmaxf(fmaxf(s0, s1), fmaxf(s2, s3));
            float e0 = __expf(s0 - m), e1 = __expf(s1 - m), e2 = __expf(s2 - m), e3 = __expf(s3 - m);
            float inv = 1.f / (e0 + e1 + e2 + e3);
            scp[r] = e0*inv; scp[r+1] = e1*inv; scp[r+2] = e2*inv; scp[r+3] = e3*inv;
        }
        __syncwarp();

        // ---- m_t (both nodes; z fully consumed, safe to overwrite b2f) ----
        #pragma unroll
        for (int nd = 0; nd < 2; nd++) {
            const float* sbase = nd ? sB : sA;
            const float* scp = nd ? scBp : scAp;
            float* fbase = nd ? fB : fA;
            float w0 = scp[t*4], w1 = scp[t*4+1], w2 = scp[t*4+2], w3 = scp[t*4+3];
            #pragma unroll
            for (int h = 0; h < 2; h++) {
                int c = h == 0 ? c1 : c2;
                float4 s0 = *(const float4*)(sbase + c);
                float4 s1 = *(const float4*)(sbase + SSTR + c);
                float4 s2 = *(const float4*)(sbase + 2 * SSTR + c);
                float4 s3 = *(const float4*)(sbase + 3 * SSTR + c);
                float4 r;
                r.x = w0*s0.x + w1*s1.x + w2*s2.x + w3*s3.x;
                r.y = w0*s0.y + w1*s1.y + w2*s2.y + w3*s3.y;
                r.z = w0*s0.z + w1*s1.z + w2*s2.z + w3*s3.z;
                r.w = w0*s0.w + w1*s1.w + w2*s2.w + w3*s3.w;
                *(float4*)(fbase + t * FSTR + c) = r;
            }
        }
        __syncwarp();

        // ---- out-proj (Wvo) dual + residual + LN1 ----
        {
            float4 r0A = *(const float4*)(bvoS + c1);
            float4 r1A = *(const float4*)(bvoS + c2);
            float4 r0B = r0A, r1B = r1A;
            const float* arA = fA + t * FSTR;
            const float* arB = fB + t * FSTR;
            for (int k4 = 0; k4 < 16; k4++) {
                float4 avA = ((const float4*)arA)[k4];
                float4 avB = ((const float4*)arB)[k4];
                #pragma unroll
                for (int kk = 0; kk < 4; kk++) {
                    const float* wrow = WvoS + (k4 * 4 + kk) * 64;
                    float4 wA = *(const float4*)(wrow + c1);
                    float4 wB = *(const float4*)(wrow + c2);
                    float aa = kk == 0 ? avA.x : kk == 1 ? avA.y : kk == 2 ? avA.z : avA.w;
                    float ab = kk == 0 ? avB.x : kk == 1 ? avB.y : kk == 2 ? avB.z : avB.w;
                    r0A.x = fmaf(aa, wA.x, r0A.x); r0A.y = fmaf(aa, wA.y, r0A.y);
                    r0A.z = fmaf(aa, wA.z, r0A.z); r0A.w = fmaf(aa, wA.w, r0A.w);
                    r1A.x = fmaf(aa, wB.x, r1A.x); r1A.y = fmaf(aa, wB.y, r1A.y);
                    r1A.z = fmaf(aa, wB.z, r1A.z); r1A.w = fmaf(aa, wB.w, r1A.w);
                    r0B.x = fmaf(ab, wA.x, r0B.x); r0B.y = fmaf(ab, wA.y, r0B.y);
                    r0B.z = fmaf(ab, wA.z, r0B.z); r0B.w = fmaf(ab, wA.w, r0B.w);
                    r1B.x = fmaf(ab, wB.x, r1B.x); r1B.y = fmaf(ab, wB.y, r1B.y);
                    r1B.z = fmaf(ab, wB.z, r1B.z); r1B.w = fmaf(ab, wB.w, r1B.w);
                }
            }
            float4 w1v = *(const float4*)(ln1wS + c1), w2v = *(const float4*)(ln1wS + c2);
            float4 b1v = *(const float4*)(ln1bS + c1), b2v = *(const float4*)(ln1bS + c2);
            // node A
            {
                float4 rs0 = *(const float4*)(srA + c1);
                float4 rs1 = *(const float4*)(srA + c2);
                float r[8];
                r[0] = r0A.x + rs0.x; r[1] = r0A.y + rs0.y; r[2] = r0A.z + rs0.z; r[3] = r0A.w + rs0.w;
                r[4] = r1A.x + rs1.x; r[5] = r1A.y + rs1.y; r[6] = r1A.z + rs1.z; r[7] = r1A.w + rs1.w;
                float sum = r[0]+r[1]+r[2]+r[3]+r[4]+r[5]+r[6]+r[7];
                sum += __shfl_xor_sync(0xffffffffu, sum, 1);
                sum += __shfl_xor_sync(0xffffffffu, sum, 2);
                sum += __shfl_xor_sync(0xffffffffu, sum, 4);
                float mean = sum * 0.015625f;
                float sq = 0.f;
                #pragma unroll
                for (int i = 0; i < 8; i++) { float dd = r[i] - mean; sq = fmaf(dd, dd, sq); }
                sq += __shfl_xor_sync(0xffffffffu, sq, 1);
                sq += __shfl_xor_sync(0xffffffffu, sq, 2);
                sq += __shfl_xor_sync(0xffffffffu, sq, 4);
                float inv = rsqrtf(sq * 0.015625f + 1e-5f);
                float4 o0, o1;
                o0.x = (r[0]-mean)*inv*w1v.x + b1v.x; o0.y = (r[1]-mean)*inv*w1v.y + b1v.y;
                o0.z = (r[2]-mean)*inv*w1v.z + b1v.z; o0.w = (r[3]-mean)*inv*w1v.w + b1v.w;
                o1.x = (r[4]-mean)*inv*w2v.x + b2v.x; o1.y = (r[5]-mean)*inv*w2v.y + b2v.y;
                o1.z = (r[6]-mean)*inv*w2v.z + b2v.z; o1.w = (r[7]-mean)*inv*w2v.w + b2v.w;
                *(float4*)(srA + c1) = o0;
                *(float4*)(srA + c2) = o1;
            }
            // node B
            {
                float4 rs0 = *(const float4*)(srB + c1);
                float4 rs1 = *(const float4*)(srB + c2);
                float r[8];
                r[0] = r0B.x + rs0.x; r[1] = r0B.y + rs0.y; r[2] = r0B.z + rs0.z; r[3] = r0B.w + rs0.w;
                r[4] = r1B.x + rs1.x; r[5] = r1B.y + rs1.y; r[6] = r1B.z + rs1.z; r[7] = r1B.w + rs1.w;
                float sum = r[0]+r[1]+r[2]+r[3]+r[4]+r[5]+r[6]+r[7];
                sum += __shfl_xor_sync(0xffffffffu, sum, 1);
                sum += __shfl_xor_sync(0xffffffffu, sum, 2);
                sum += __shfl_xor_sync(0xffffffffu, sum, 4);
                float mean = sum * 0.015625f;
                float sq = 0.f;
                #pragma unroll
                for (int i = 0; i < 8; i++) { float dd = r[i] - mean; sq = fmaf(dd, dd, sq); }
                sq += __shfl_xor_sync(0xffffffffu, sq, 1);
                sq += __shfl_xor_sync(0xffffffffu, sq, 2);
                sq += __shfl_xor_sync(0xffffffffu, sq, 4);
                float inv = rsqrtf(sq * 0.015625f + 1e-5f);
                float4 o0, o1;
                o0.x = (r[0]-mean)*inv*w1v.x + b1v.x; o0.y = (r[1]-mean)*inv*w1v.y + b1v.y;
                o0.z = (r[2]-mean)*inv*w1v.z + b1v.z; o0.w = (r[3]-mean)*inv*w1v.w + b1v.w;
                o1.x = (r[4]-mean)*inv*w2v.x + b2v.x; o1.y = (r[5]-mean)*inv*w2v.y + b2v.y;
                o1.z = (r[6]-mean)*inv*w2v.z + b2v.z; o1.w = (r[7]-mean)*inv*w2v.w + b2v.w;
                *(float4*)(srB + c1) = o0;
                *(float4*)(srB + c2) = o1;
            }
        }
        __syncwarp();

        // ---- FF1 + gelu, dual, 2 output halves ----
        #pragma unroll
        for (int hh = 0; hh < 2; hh++) {
            int i0 = hh * 2;
            float4 gA0 = *(const float4*)(b1S + 32 * i0 + c1);
            float4 gA1 = *(const float4*)(b1S + 32 * (i0 + 1) + c1);
            float4 gB0 = gA0, gB1 = gA1;
            for (int k4 = 0; k4 < 16; k4++) {
                float4 xvA = ((const float4*)srA)[k4];
                float4 xvB = ((const float4*)srB)[k4];
                #pragma unroll
                for (int kk = 0; kk < 4; kk++) {
                    const float* wrow = W1S + (k4 * 4 + kk) * 128;
                    float4 w0 = *(const float4*)(wrow + 32 * i0 + c1);
                    float4 w1 = *(const float4*)(wrow + 32 * (i0 + 1) + c1);
                    float xa = kk == 0 ? xvA.x : kk == 1 ? xvA.y : kk == 2 ? xvA.z : xvA.w;
                    float xb = kk == 0 ? xvB.x : kk == 1 ? xvB.y : kk == 2 ? xvB.z : xvB.w;
                    gA0.x = fmaf(xa, w0.x, gA0.x); gA0.y = fmaf(xa, w0.y, gA0.y);
                    gA0.z = fmaf(xa, w0.z, gA0.z); gA0.w = fmaf(xa, w0.w, gA0.w);
                    gA1.x = fmaf(xa, w1.x, gA1.x); gA1.y = fmaf(xa, w1.y, gA1.y);
                    gA1.z = fmaf(xa, w1.z, gA1.z); gA1.w = fmaf(xa, w1.w, gA1.w);
                    gB0.x = fmaf(xb, w0.x, gB0.x); gB0.y = fmaf(xb, w0.y, gB0.y);
                    gB0.z = fmaf(xb, w0.z, gB0.z); gB0.w = fmaf(xb, w0.w, gB0.w);
                    gB1.x = fmaf(xb, w1.x, gB1.x); gB1.y = fmaf(xb, w1.y, gB1.y);
                    gB1.z = fmaf(xb, w1.z, gB1.z); gB1.w = fmaf(xb, w1.w, gB1.w);
                }
            }
            #pragma unroll
            for (int v = 0; v < 4; v++) {
                float4* pr = v == 0 ? &gA0 : v == 1 ? &gA1 : v == 2 ? &gB0 : &gB1;
                pr->x = 0.5f * pr->x * (1.0f + erff(pr->x * 0.70710678118f));
                pr->y = 0.5f * pr->y * (1.0f + erff(pr->y * 0.70710678118f));
                pr->z = 0.5f * pr->z * (1.0f + erff(pr->z * 0.70710678118f));
                pr->w = 0.5f * pr->w * (1.0f + erff(pr->w * 0.70710678118f));
            }
            *(float4*)(fA + t * FSTR + 32 * i0 + c1)       = gA0;
            *(float4*)(fA + t * FSTR + 32 * (i0 + 1) + c1) = gA1;
            *(float4*)(fB + t * FSTR + 32 * i0 + c1)       = gB0;
            *(float4*)(fB + t * FSTR + 32 * (i0 + 1) + c1) = gB1;
        }
        __syncwarp();

        // ---- FF2 dual + residual + LN2 + token mean ----
        {
            float4 f0A = *(const float4*)(b2S + c1);
            float4 f1A = *(const float4*)(b2S + c2);
            float4 f0B = f0A, f1B = f1A;
            const float* grA = fA + t * FSTR;
            const float* grB = fB + t * FSTR;
            for (int k4 = 0; k4 < 32; k4++) {
                float4 gvA = ((const float4*)grA)[k4];
                float4 gvB = ((const float4*)grB)[k4];
                #pragma unroll
                for (int kk = 0; kk < 4; kk++) {
                    const float* wrow = W2S + (k4 * 4 + kk) * 64;
                    float4 wA = *(const float4*)(wrow + c1);
                    float4 wB = *(const float4*)(wrow + c2);
                    float ga = kk == 0 ? gvA.x : kk == 1 ? gvA.y : kk == 2 ? gvA.z : gvA.w;
                    float gb = kk == 0 ? gvB.x : kk == 1 ? gvB.y : kk == 2 ? gvB.z : gvB.w;
                    f0A.x = fmaf(ga, wA.x, f0A.x); f0A.y = fmaf(ga, wA.y, f0A.y);
                    f0A.z = fmaf(ga, wA.z, f0A.z); f0A.w = fmaf(ga, wA.w, f0A.w);
                    f1A.x = fmaf(ga, wB.x, f1A.x); f1A.y = fmaf(ga, wB.y, f1A.y);
                    f1A.z = fmaf(ga, wB.z, f1A.z); f1A.w = fmaf(ga, wB.w, f1A.w);
                    f0B.x = fmaf(gb, wA.x, f0B.x); f0B.y = fmaf(gb, wA.y, f0B.y);
                    f0B.z = fmaf(gb, wA.z, f0B.z); f0B.w = fmaf(gb, wA.w, f0B.w);
                    f1B.x = fmaf(gb, wB.x, f1B.x); f1B.y = fmaf(gb, wB.y, f1B.y);
                    f1B.z = fmaf(gb, wB.z, f1B.z); f1B.w = fmaf(gb, wB.w, f1B.w);
                }
            }
            #pragma unroll
            for (int nd = 0; nd < 2; nd++) {
                const float* srp = nd ? srB : srA;
                float* hbp = nd ? hbB : hbA;
                float4 q0 = nd ? f0B : f0A;
                float4 q1 = nd ? f1B : f1A;
                float4 rs0 = *(const float4*)(srp + c1);
                float4 rs1 = *(const float4*)(srp + c2);
                float f[8];
                f[0] = q0.x + rs0.x; f[1] = q0.y + rs0.y; f[2] = q0.z + rs0.z; f[3] = q0.w + rs0.w;
                f[4] = q1.x + rs1.x; f[5] = q1.y + rs1.y; f[6] = q1.z + rs1.z; f[7] = q1.w + rs1.w;
                float sum = f[0]+f[1]+f[2]+f[3]+f[4]+f[5]+f[6]+f[7];
                sum += __shfl_xor_sync(0xffffffffu, sum, 1);
                sum += __shfl_xor_sync(0xffffffffu, sum, 2);
                sum += __shfl_xor_sync(0xffffffffu, sum, 4);
                float mean = sum * 0.015625f;
                float sq = 0.f;
                #pragma unroll
                for (int i = 0; i < 8; i++) { float dd = f[i] - mean; sq = fmaf(dd, dd, sq); }
                sq += __shfl_xor_sync(0xffffffffu, sq, 1);
                sq += __shfl_xor_sync(0xffffffffu, sq, 2);
                sq += __shfl_xor_sync(0xffffffffu, sq, 4);
                float inv = rsqrtf(sq * 0.015625f + 1e-5f);
                float x2v[8];
                #pragma unroll
                for (int i = 0; i < 8; i++) {
                    int j = (i < 4) ? (c1 + i) : (c2 + i - 4);
                    x2v[i] = (f[i] - mean) * inv * ln2wS[j] + ln2bS[j];
                }
                #pragma unroll
                for (int i = 0; i < 8; i++) {
                    float v = x2v[i];
                    v += __shfl_xor_sync(0xffffffffu, v, 8);
                    v += __shfl_xor_sync(0xffffffffu, v, 16);
                    x2v[i] = v * 0.25f;
                }
                if (t == 0) {
                    *(float4*)(hbp + c1) = make_float4(x2v[0], x2v[1], x2v[2], x2v[3]);
                    *(float4*)(hbp + c2) = make_float4(x2v[4], x2v[5], x2v[6], x2v[7]);
                }
            }
        }
        __syncwarp();

        // ---- classifier dual (weight loads shared) ----
        {
            float o0A = bclsS[l], o0B = o0A;
            float o1A = bclsS[32 + g], o1B = o1A;
            #pragma unroll 4
            for (int k4 = 0; k4 < 16; k4++) {
                float4 hvA = ((const float4*)hbA)[k4];
                float4 hvB = ((const float4*)hbB)[k4];
                const float* wr = WclsS + k4 * 160;
                float w00 = wr[l],        w01 = wr[32 + g];
                float w10 = wr[40 + l],   w11 = wr[72 + g];
                float w20 = wr[80 + l],   w21 = wr[112 + g];
                float w30 = wr[120 + l],  w31 = wr[152 + g];
                o0A = fmaf(hvA.x, w00, o0A); o0B = fmaf(hvB.x, w00, o0B);
                o1A = fmaf(hvA.x, w01, o1A); o1B = fmaf(hvB.x, w01, o1B);
                o0A = fmaf(hvA.y, w10, o0A); o0B = fmaf(hvB.y, w10, o0B);
                o1A = fmaf(hvA.y, w11, o1A); o1B = fmaf(hvB.y, w11, o1B);
                o0A = fmaf(hvA.z, w20, o0A); o0B = fmaf(hvB.z, w20, o0B);
                o1A = fmaf(hvA.z, w21, o1A); o1B = fmaf(hvB.z, w21, o1B);
                o0A = fmaf(hvA.w, w30, o0A); o0B = fmaf(hvB.w, w30, o0B);
                o1A = fmaf(hvA.w, w31, o1A); o1B = fmaf(hvB.w, w31, o1B);
            }
            out[(size_t)n0 * 40 + l] = o0A;
            out[(size_t)(n0 + 1) * 40 + l] = o0B;
            if (l < 8) {
                out[(size_t)n0 * 40 + 32 + l] = o1A;
                out[(size_t)(n0 + 1) * 40 + 32 + l] = o1B;
            }
        }
        __syncwarp();
    }
}

extern "C" void kernel_launch(void* const* d_in, const int* in_sizes, int n_in,
                              void* d_out, int out_size) {
    const float* x     = (const float*)d_in[0];
    const int*   ei    = (const int*)d_in[1];
    const float* W_in  = (const float*)d_in[2];
    const float* b_in  = (const float*)d_in[3];
    const float* sg_W  = (const float*)d_in[4];
    const float* sg_b  = (const float*)d_in[5];
    const float* inW   = (const float*)d_in[6];
    const float* inb   = (const float*)d_in[7];
    const float* Wout  = (const float*)d_in[8];
    const float* bout  = (const float*)d_in[9];
    const float* W1    = (const float*)d_in[10];
    const float* b1    = (const float*)d_in[11];
    const float* W2    = (const float*)d_in[12];
    const float* b2    = (const float*)d_in[13];
    const float* ln1w  = (const float*)d_in[14];
    const float* ln1b  = (const float*)d_in[15];
    const float* ln2w  = (const float*)d_in[16];
    const float* ln2b  = (const float*)d_in[17];
    const float* Wcls  = (const float*)d_in[18];
    const float* bcls  = (const float*)d_in[19];
    float* out = (float*)d_out;

    // former smem: (27752 + 16*2*896) * 4 = 225,696 B
    cudaFuncSetAttribute(k_in_linear, cudaFuncAttributeMaxDynamicSharedMemorySize, 99584);
    cudaFuncSetAttribute(k_former,    cudaFuncAttributeMaxDynamicSharedMemorySize, 225696);

    // 1: CSR build + folded matrices (persistent)
    k_build<<<148, 256>>>(ei, ei + Ee, inW, inb, Wout, bout);
    // 2: h0 + seq slot 0
    k_in_linear<<<592, 256, 99584>>>(x, W_in, b_in);
    // 3: all 3 hops (persistent, grid barriers)
    k_prop_all<<<592, 256>>>(sg_W, sg_b);
    // 4: fused transformer, 2 nodes/warp  (launch #4 -> profiled)
    k_former<<<148, FT, 225696>>>(W1, b1, W2, b2, ln1w, ln1b, ln2w, ln2b, Wcls, bcls, out);
}